// round 17
// baseline (speedup 1.0000x reference)
#include <cuda_runtime.h>
#include <cuda_fp16.h>
#include <mma.h>
#include <cstdint>

using namespace nvcuda;

#define N_NODES    50000
#define N_EDGES    800000
#define IN_DIM     128
#define HID_DIM    64
#define OUT_DIM    64
#define NUM_GRAPHS 512
#define SCAN_T     1024
#define KC         64

// ---------------- scratch (device globals; no allocations allowed) ----------------
__device__ __align__(16) int     g_ctr   [2 * N_NODES];    // [0:N)=degc, [N:2N)=cursor
__device__ __align__(16) int     g_row   [N_NODES + 1];    // CSR row offsets
__device__ __align__(16) float   g_dinv  [N_NODES];
__device__ __align__(16) int     g_srci  [N_EDGES];        // CSR payload: src index only
__device__ __align__(16) int     g_gstart[NUM_GRAPHS + 1]; // graph segment boundaries
__device__ __align__(16) __half2 g_hh    [N_NODES * 32];   // fp16 h = (A@W+b)*dinv[row]
__device__ __align__(16) float   g_agg1  [N_NODES * 64];   // relu(agg) layer 1 (fp32)
__device__ __align__(16) float   g_agg2  [N_NODES * 64];   // relu(agg) layer 2 (fp32)

// ---------------- cp.async helpers ----------------
__device__ __forceinline__ void cp_async16(unsigned saddr, const void* gptr, bool pred) {
    int bytes = pred ? 16 : 0;
    asm volatile("cp.async.cg.shared.global [%0], [%1], 16, %2;\n"
                 :: "r"(saddr), "l"(gptr), "r"(bytes));
}
#define CP_COMMIT()  asm volatile("cp.async.commit_group;\n" ::: "memory")
#define CP_WAIT(n)   asm volatile("cp.async.wait_group %0;\n" :: "n"(n) : "memory")

// ---------------- prep kernels ----------------
// count edges per dst; 4 edges per thread via int4 (MLP=4).
__global__ void __launch_bounds__(256) count_kernel(const int* __restrict__ ei) {
    int t = blockIdx.x * blockDim.x + threadIdx.x;
    if (t >= N_EDGES / 4) return;
    int4 d4 = ((const int4*)(ei + N_EDGES))[t];
    atomicAdd(&g_ctr[d4.x], 1);
    atomicAdd(&g_ctr[d4.y], 1);
    atomicAdd(&g_ctr[d4.z], 1);
    atomicAdd(&g_ctr[d4.w], 1);
}

// single-block exclusive scan of counts -> g_row; also computes g_dinv.
__global__ void __launch_bounds__(SCAN_T) scan_kernel() {
    __shared__ int sp[SCAN_T];
    int t = threadIdx.x;
    const int C = (N_NODES + SCAN_T - 1) / SCAN_T;   // 49
    int beg = t * C;
    int end = min(beg + C, N_NODES);
    int sum = 0;
    for (int i = beg; i < end; i++) sum += g_ctr[i];
    sp[t] = sum;
    __syncthreads();
    for (int off = 1; off < SCAN_T; off <<= 1) {
        int v = (t >= off) ? sp[t - off] : 0;
        __syncthreads();
        sp[t] += v;
        __syncthreads();
    }
    int excl = sp[t] - sum;
    for (int i = beg; i < end; i++) {
        int c = g_ctr[i];
        g_row[i]  = excl;
        g_dinv[i] = rsqrtf(fmaxf((float)c, 1.0f));
        excl += c;
    }
    if (t == SCAN_T - 1) g_row[N_NODES] = sp[SCAN_T - 1];
}

// counting-sort fill, 4 edges per thread (4 independent chains).
// Also graph boundaries from sorted batch (thread id doubles as node id).
__global__ void __launch_bounds__(256) fill_kernel(const int* __restrict__ ei,
                                                   const int* __restrict__ batch) {
    int t = blockIdx.x * blockDim.x + threadIdx.x;
    if (t < N_NODES) {
        int b  = batch[t];
        int bp = (t == 0) ? -1 : batch[t - 1];
        for (int g = bp + 1; g <= b; g++) g_gstart[g] = t;
        if (t == N_NODES - 1)
            for (int g = b + 1; g <= NUM_GRAPHS; g++) g_gstart[g] = N_NODES;
    }
    if (t >= N_EDGES / 4) return;
    int* cur = g_ctr + N_NODES;
    int4 s4 = ((const int4*)ei)[t];
    int4 d4 = ((const int4*)(ei + N_EDGES))[t];
    int p0 = g_row[d4.x] + atomicAdd(&cur[d4.x], 1);
    int p1 = g_row[d4.y] + atomicAdd(&cur[d4.y], 1);
    int p2 = g_row[d4.z] + atomicAdd(&cur[d4.z], 1);
    int p3 = g_row[d4.w] + atomicAdd(&cur[d4.w], 1);
    g_srci[p0] = s4.x;
    g_srci[p1] = s4.y;
    g_srci[p2] = s4.z;
    g_srci[p3] = s4.w;
}

// ---------------- tensor-core GEMM with cp.async pipeline ----------------
// g_hh[M,64](fp16) = ((A[M,KTOT] @ W[KTOT,64]) + bias) * dinv[row]
// 128x64 tile, 8 warps x (16x64), m16n16k16 HMMA fp32-accum.
// A streams gmem->smem fp32 via 2-stage cp.async; converted to fp16 in smem.
template<int KTOT, bool A_IS_AGG1>
__global__ void __launch_bounds__(256) gemm_tc_kernel(const float* __restrict__ Ap,
                                                      const float* __restrict__ W,
                                                      const float* __restrict__ bias) {
    extern __shared__ char smraw[];
    float*  aSt = (float*)smraw;                              // [2][128*KC] fp32 stages
    __half* aH  = (__half*)(smraw + 2 * 128 * KC * 4);        // [128*72] fp16 A tile
    __half* wH  = aH + 128 * 72;                              // [KTOT*72] fp16 W
    float*  oSt = aSt;                                        // epilogue staging (reuse)

    const float* A = A_IS_AGG1 ? g_agg1 : Ap;
    int tid  = threadIdx.x;
    int wid  = tid >> 5;
    int row0 = blockIdx.x * 128;
    unsigned aStBase = (unsigned)__cvta_generic_to_shared(aSt);

    // load + convert W once (small)
    for (int idx = tid; idx < KTOT * 16; idx += 256) {        // float4 granules
        int kr = idx >> 4, c4 = idx & 15;
        float4 v = *(const float4*)(W + (size_t)kr * 64 + c4 * 4);
        __half2 h0 = __floats2half2_rn(v.x, v.y);
        __half2 h1 = __floats2half2_rn(v.z, v.w);
        *(uint2*)(wH + kr * 72 + c4 * 4) = make_uint2(*(unsigned*)&h0, *(unsigned*)&h1);
    }

    wmma::fragment<wmma::accumulator, 16, 16, 16, float> cf[4];
#pragma unroll
    for (int n = 0; n < 4; n++) wmma::fill_fragment(cf[n], 0.0f);

    const int NCH = KTOT / KC;

    // issue one stage of A (128 rows x KC fp32) via cp.async
    auto issue = [&](int stage, int k0) {
#pragma unroll
        for (int i = 0; i < 8; i++) {
            int idx = tid + i * 256;              // 0..2047
            int r   = idx >> 4;                   // 0..127
            int c4  = idx & 15;                   // 0..15
            int gr  = row0 + r;
            bool ok = gr < N_NODES;
            const void* g = A + (size_t)(ok ? gr : 0) * KTOT + k0 + c4 * 4;
            unsigned sa = aStBase + (unsigned)(stage * 128 * KC + r * KC + c4 * 4) * 4u;
            cp_async16(sa, g, ok);
        }
        CP_COMMIT();
    };

    issue(0, 0);
    for (int c = 0; c < NCH; c++) {
        if (c + 1 < NCH) { issue((c + 1) & 1, (c + 1) * KC); CP_WAIT(1); }
        else             { CP_WAIT(0); }
        __syncthreads();
        // convert fp32 stage -> fp16 aH
        const float* st = aSt + (c & 1) * 128 * KC;
#pragma unroll
        for (int i = 0; i < 8; i++) {
            int idx = tid + i * 256;
            int r   = idx >> 4;
            int c4  = idx & 15;
            float4 v = *(const float4*)(st + r * KC + c4 * 4);
            __half2 h0 = __floats2half2_rn(v.x, v.y);
            __half2 h1 = __floats2half2_rn(v.z, v.w);
            *(uint2*)(aH + r * 72 + c4 * 4) = make_uint2(*(unsigned*)&h0, *(unsigned*)&h1);
        }
        __syncthreads();
#pragma unroll
        for (int kk = 0; kk < KC / 16; kk++) {
            wmma::fragment<wmma::matrix_a, 16, 16, 16, __half, wmma::row_major> af;
            wmma::load_matrix_sync(af, aH + (wid * 16) * 72 + kk * 16, 72);
#pragma unroll
            for (int n = 0; n < 4; n++) {
                wmma::fragment<wmma::matrix_b, 16, 16, 16, __half, wmma::row_major> bf;
                wmma::load_matrix_sync(bf, wH + (c * KC + kk * 16) * 72 + n * 16, 72);
                wmma::mma_sync(cf[n], af, bf, cf[n]);
            }
        }
        __syncthreads();
    }

    // stage accumulators through smem (reuse aSt region)
#pragma unroll
    for (int n = 0; n < 4; n++)
        wmma::store_matrix_sync(oSt + (wid * 16) * 64 + n * 16, cf[n], 64,
                                wmma::mem_row_major);
    __syncthreads();

    // epilogue: bias + dinv scale, fp16 out
#pragma unroll
    for (int i = 0; i < 8; i++) {
        int idx = tid + i * 256;
        int r   = idx >> 4;
        int c4  = idx & 15;
        int gr  = row0 + r;
        if (gr < N_NODES) {
            float4 v  = *(const float4*)(oSt + r * 64 + c4 * 4);
            float4 bv = *(const float4*)(bias + c4 * 4);
            float dv  = g_dinv[gr];
            __half2 h0 = __floats2half2_rn((v.x + bv.x) * dv, (v.y + bv.y) * dv);
            __half2 h1 = __floats2half2_rn((v.z + bv.z) * dv, (v.w + bv.w) * dv);
            *(uint2*)(g_hh + (size_t)gr * 32 + c4 * 2) =
                make_uint2(*(unsigned*)&h0, *(unsigned*)&h1);
        }
    }
}

// ---------------- pull aggregation ----------------
// one warp per node; lane owns 2 dims (half2 gather). 8-edge unroll (MLP=8).
template<bool TO_AGG2>
__global__ void __launch_bounds__(256) agg_kernel() {
    int node = (blockIdx.x * 256 + threadIdx.x) >> 5;
    if (node >= N_NODES) return;
    int lane = threadIdx.x & 31;
    int s0 = g_row[node];
    int s1 = g_row[node + 1];

    float2 a0 = make_float2(0.f, 0.f);
    float2 a1 = make_float2(0.f, 0.f);
    float2 a2 = make_float2(0.f, 0.f);
    float2 a3 = make_float2(0.f, 0.f);
    int e = s0;
    for (; e + 7 < s1; e += 8) {
        int i0 = g_srci[e + 0];
        int i1 = g_srci[e + 1];
        int i2 = g_srci[e + 2];
        int i3 = g_srci[e + 3];
        int i4 = g_srci[e + 4];
        int i5 = g_srci[e + 5];
        int i6 = g_srci[e + 6];
        int i7 = g_srci[e + 7];
        float2 v0 = __half22float2(g_hh[(size_t)i0 * 32 + lane]);
        float2 v1 = __half22float2(g_hh[(size_t)i1 * 32 + lane]);
        float2 v2 = __half22float2(g_hh[(size_t)i2 * 32 + lane]);
        float2 v3 = __half22float2(g_hh[(size_t)i3 * 32 + lane]);
        float2 v4 = __half22float2(g_hh[(size_t)i4 * 32 + lane]);
        float2 v5 = __half22float2(g_hh[(size_t)i5 * 32 + lane]);
        float2 v6 = __half22float2(g_hh[(size_t)i6 * 32 + lane]);
        float2 v7 = __half22float2(g_hh[(size_t)i7 * 32 + lane]);
        a0.x += v0.x + v4.x; a0.y += v0.y + v4.y;
        a1.x += v1.x + v5.x; a1.y += v1.y + v5.y;
        a2.x += v2.x + v6.x; a2.y += v2.y + v6.y;
        a3.x += v3.x + v7.x; a3.y += v3.y + v7.y;
    }
    for (; e < s1; e++) {
        float2 v = __half22float2(g_hh[(size_t)g_srci[e] * 32 + lane]);
        a0.x += v.x; a0.y += v.y;
    }
    float dv = g_dinv[node];
    float sx = ((a0.x + a1.x) + (a2.x + a3.x)) * dv;
    float sy = ((a0.y + a1.y) + (a2.y + a3.y)) * dv;
    float2 r = make_float2(fmaxf(sx, 0.f), fmaxf(sy, 0.f));
    float* dst = TO_AGG2 ? g_agg2 : g_agg1;
    *(float2*)(dst + (size_t)node * 64 + lane * 2) = r;
}

// pooling: one block per graph over its contiguous node range; mean of g_agg2.
__global__ void __launch_bounds__(256) pool_kernel(float* __restrict__ out) {
    __shared__ float sm[256];
    int g = blockIdx.x;
    int t = threadIdx.x;
    int d = t & 63;
    int r = t >> 6;        // 0..3
    int s0 = g_gstart[g];
    int s1 = g_gstart[g + 1];
    float acc = 0.f;
    for (int n = s0 + r; n < s1; n += 4)
        acc += g_agg2[(size_t)n * 64 + d];
    sm[t] = acc;
    __syncthreads();
    if (t < 64) {
        float v = sm[t] + sm[t + 64] + sm[t + 128] + sm[t + 192];
        float c = (float)(s1 - s0);
        out[(size_t)g * 64 + t] = v / fmaxf(c, 1.0f);
    }
}

// ---------------- launch ----------------
extern "C" void kernel_launch(void* const* d_in, const int* in_sizes, int n_in,
                              void* d_out, int out_size) {
    // Identify inputs by element count (robust to metadata ordering).
    const float *x = nullptr, *W1 = nullptr, *b1 = nullptr, *W2 = nullptr, *b2 = nullptr;
    const int   *ei = nullptr, *batch = nullptr;
    for (int i = 0; i < n_in; i++) {
        switch (in_sizes[i]) {
            case N_NODES * IN_DIM:   x     = (const float*)d_in[i]; break;
            case 2 * N_EDGES:        ei    = (const int*)d_in[i];   break;
            case N_NODES:            batch = (const int*)d_in[i];   break;
            case IN_DIM * HID_DIM:   W1    = (const float*)d_in[i]; break;
            case HID_DIM * OUT_DIM:  W2    = (const float*)d_in[i]; break;
            case HID_DIM:
                if (!b1) b1 = (const float*)d_in[i];
                else     b2 = (const float*)d_in[i];
                break;
            default: break;
        }
    }
    float* out = (float*)d_out;

    // one memset zeroes both counters (degc + cursor)
    void* ctr_ptr = nullptr;
    cudaGetSymbolAddress(&ctr_ptr, g_ctr);
    cudaMemsetAsync(ctr_ptr, 0, 2 * N_NODES * sizeof(int));

    const int SMEM1 = 2 * 128 * KC * 4 + 128 * 72 * 2 + IN_DIM  * 72 * 2;  // 102400
    const int SMEM2 = 2 * 128 * KC * 4 + 128 * 72 * 2 + HID_DIM * 72 * 2;  //  93184
    cudaFuncSetAttribute(gemm_tc_kernel<IN_DIM, false>,
                         cudaFuncAttributeMaxDynamicSharedMemorySize, SMEM1);
    cudaFuncSetAttribute(gemm_tc_kernel<HID_DIM, true>,
                         cudaFuncAttributeMaxDynamicSharedMemorySize, SMEM2);

    const int T = 256;
    count_kernel<<<(N_EDGES / 4 + T - 1) / T, T>>>(ei);
    scan_kernel <<<1, SCAN_T>>>();
    fill_kernel <<<(N_EDGES / 4 + T - 1) / T, T>>>(ei, batch);

    // layer 1
    gemm_tc_kernel<IN_DIM, false><<<(N_NODES + 127) / 128, T, SMEM1>>>(x, W1, b1);
    agg_kernel<false><<<(N_NODES * 32 + T - 1) / T, T>>>();

    // layer 2
    gemm_tc_kernel<HID_DIM, true><<<(N_NODES + 127) / 128, T, SMEM2>>>(nullptr, W2, b2);
    agg_kernel<true><<<(N_NODES * 32 + T - 1) / T, T>>>();

    // pooling
    pool_kernel<<<NUM_GRAPHS, T>>>(out);
}